// round 11
// baseline (speedup 1.0000x reference)
#include <cuda_runtime.h>

// SegGPS_66949950210076
// out[b] = sum_m prod_l eps[idx[b,l], m, l, nup[b,l], ndn[b,l]]
// B=8192, L=64, M=64, LOCAL_DIM=4, eps (4,64,64,65,65) fp32.
//
// R8: hybrid transpose into T[cell][idx][m] (256B m-contiguous, L2-res).
//  l <  32: unconditionally transposed (smem, coalesced) -- no flags, so the
//           catastrophically hot small-l flag cells are never stored at all.
//  l >= 32: flag kernel (test-before-set byte flags) + warp-ballot transpose
//           that self-clears its flags.
//  gather: warp/batch, float4 lane-split (proven 15.5us shape).

#define B_SZ   8192
#define L_SZ   64
#define IDX_STRIDE 17305600   // M*L*65*65
#define M_STRIDE   270400     // L*65*65
#define L_STRIDE   4225       // 65*65
#define CELLS  89440          // sum_{k=1..64} k^2
#define T_ELEMS (CELLS * 256)

__device__ __align__(256) float g_T[T_ELEMS]; // 91.6 MB scratch (static)
__device__ unsigned char g_flags[4][CELLS];   // zero-init; only l>=32 used;
                                              // transposeB self-clears
__device__ __forceinline__ int cell_off(int l) {
    return l * (l + 1) * (2 * l + 1) / 6;     // sum_{j=1..l} j^2
}
__device__ __forceinline__ float4 mul4(float4 a, float4 b) {
    return make_float4(a.x * b.x, a.y * b.y, a.z * b.z, a.w * b.w);
}

// Per-warp dtype probe. Indices are logically int64 (ref) but JAX x64-off
// emits int32. Under int64 LE every odd 32-bit word is 0 (values < 4); under
// int32 odd words are random in [0,4). Probe 64 odd words of a fixed
// 128-word window within the first 524288 words (in-bounds either way).
// P(false int64 | int32) = 0.25^64 per warp.
__device__ __forceinline__ int probe_is_int32(const unsigned* __restrict__ w,
                                              int b, int lane) {
    int base = (b & 4095) * 128;
    unsigned x = w[base + 2 * lane + 1] | w[base + 64 + 2 * lane + 1];
    return __ballot_sync(0xffffffffu, x != 0u) != 0u;
}

// Per-warp scan of one batch: two ballots cover all 64 sites.
__device__ __forceinline__ void scan_batch(
    const void* idx_raw, int is32, int b, int lane,
    int& v0, int& v1, int& cell0, int& cell1)
{
    if (is32) {
        const int* p = (const int*)idx_raw + b * L_SZ;
        v0 = p[lane];  v1 = p[lane + 32];
    } else {
        const long long* p = (const long long*)idx_raw + (size_t)b * L_SZ;
        v0 = (int)p[lane];  v1 = (int)p[lane + 32];
    }
    unsigned bu0 = __ballot_sync(0xffffffffu, v0 & 1);
    unsigned bd0 = __ballot_sync(0xffffffffu, v0 & 2);
    unsigned bu1 = __ballot_sync(0xffffffffu, v1 & 1);
    unsigned bd1 = __ballot_sync(0xffffffffu, v1 & 2);
    unsigned mlt = (1u << lane) - 1u;
    int nup0 = __popc(bu0 & mlt),               ndn0 = __popc(bd0 & mlt);
    int nup1 = __popc(bu0) + __popc(bu1 & mlt), ndn1 = __popc(bd0) + __popc(bd1 & mlt);
    cell0 = cell_off(lane)      + nup0 * (lane + 1)  + ndn0;
    cell1 = cell_off(lane + 32) + nup1 * (lane + 33) + ndn1;
}

// ---- flag touched cells, l>=32 only, test-before-set ----
__global__ __launch_bounds__(256) void flag_kernel(const void* __restrict__ idx_raw) {
    int lane = threadIdx.x & 31;
    int b = blockIdx.x * 8 + (threadIdx.x >> 5);
    int is32 = probe_is_int32((const unsigned*)idx_raw, b, lane);
    int v0, v1, c0, c1;
    scan_batch(idx_raw, is32, b, lane, v0, v1, c0, c1);
    (void)v0; (void)c0;                       // l<32 sites need no flags
    if (!g_flags[v1][c1]) g_flags[v1][c1] = 1;
}

// ---- transpose A: l<32, unconditional, smem-coalesced ----
__global__ __launch_bounds__(256) void transposeA_kernel(const float* __restrict__ eps) {
    const int l = blockIdx.x, nup = blockIdx.y, idx = blockIdx.z;
    if (nup > l) return;                      // l<32 so nup<32
    const int nv = l + 1;                     // <= 32
    const int cellbase = cell_off(l) + nup * nv;

    __shared__ float sm[64][33];              // [m][ndn], nv<=32, pad

    const int tid = threadIdx.x;
    const int c   = tid & 31;                 // ndn for read phase
    const int r8  = tid >> 5;                 // m sub-block 0..7

    const float* src = eps + idx * IDX_STRIDE + l * L_STRIDE + nup * 65;
    if (c < nv) {
        #pragma unroll
        for (int mb = 0; mb < 64; mb += 8) {
            int m = mb + r8;
            sm[m][c] = src[m * M_STRIDE + c];     // coalesced along ndn
        }
    }
    __syncthreads();

    const int cm = tid & 63;                  // m for write phase
    const int r4 = tid >> 6;                  // 4 ndn per pass
    float* dst = g_T + (size_t)cellbase * 256 + idx * 64;
    #pragma unroll
    for (int nb = 0; nb < 32; nb += 4) {
        int ndn = nb + r4;
        if (ndn < nv)
            dst[ndn * 256 + cm] = sm[cm][ndn];    // 256B coalesced
    }
}

// ---- transpose B: l>=32, warp-ballot on flags, self-clearing ----
__global__ __launch_bounds__(128) void transposeB_kernel(const float* __restrict__ eps) {
    const int l = 32 + blockIdx.x, nup = blockIdx.y;
    if (nup > l) return;
    const int nv = l + 1;
    const int cellbase = cell_off(l) + nup * nv;

    const int lane = threadIdx.x & 31;
    const int idx  = threadIdx.x >> 5;        // warp = idx value 0..3

    unsigned char* fl = &g_flags[idx][cellbase];
    int f0 = (lane < nv)      ? fl[lane]      : 0;
    int f1 = (lane + 32 < nv) ? fl[lane + 32] : 0;
    unsigned b0 = __ballot_sync(0xffffffffu, f0);
    unsigned b1 = __ballot_sync(0xffffffffu, f1);
    if (f0) fl[lane]      = 0;                // restore all-zero invariant
    if (f1) fl[lane + 32] = 0;

    unsigned long long m = (unsigned long long)b0
                         | ((unsigned long long)b1 << 32);
    if (!m) return;

    const float* src = eps + idx * IDX_STRIDE + l * L_STRIDE + nup * 65;
    const float* s0 = src + lane * M_STRIDE;          // m = lane
    const float* s1 = src + (lane + 32) * M_STRIDE;   // m = lane+32
    float* dstbase = g_T + (size_t)cellbase * 256 + idx * 64;

    while (m) {
        int n0 = __ffsll(m) - 1;  m &= m - 1;
        int n1 = -1;
        if (m) { n1 = __ffsll(m) - 1;  m &= m - 1; }
        float a0 = __ldg(s0 + n0);
        float a1 = __ldg(s1 + n0);
        float c0 = 0.f, c1 = 0.f;
        if (n1 >= 0) { c0 = __ldg(s0 + n1); c1 = __ldg(s1 + n1); }
        float* d0 = dstbase + n0 * 256;
        d0[lane]      = a0;                   // 256B coalesced per cell
        d0[lane + 32] = a1;
        if (n1 >= 0) {
            float* d1 = dstbase + n1 * 256;
            d1[lane]      = c0;
            d1[lane + 32] = c1;
        }
    }
}

// ---- gather: warp per batch; float4, lane-split (even/odd sites) ----
__global__ __launch_bounds__(256) void seggps_kernel(
    const void* __restrict__ idx_raw,
    float*      __restrict__ out)
{
    __shared__ int soffs[8][64];

    const int lane = threadIdx.x & 31;
    const int w    = threadIdx.x >> 5;
    const int b    = blockIdx.x * 8 + w;

    int is32 = probe_is_int32((const unsigned*)idx_raw, b, lane);
    int v0, v1, c0, c1;
    scan_batch(idx_raw, is32, b, lane, v0, v1, c0, c1);
    soffs[w][lane]      = c0 * 256 + v0 * 64;
    soffs[w][lane + 32] = c1 * 256 + v1 * 64;
    __syncwarp();

    const int half = lane >> 4;               // 0: even sites, 1: odd sites
    const int q    = lane & 15;               // m-quad

    float4 a0 = make_float4(1.f, 1.f, 1.f, 1.f), a1 = a0, a2 = a0, a3 = a0;
    #pragma unroll
    for (int i = 0; i < 32; i += 4) {
        float4 x0 = __ldg((const float4*)(g_T + soffs[w][2 * (i + 0) + half]) + q);
        float4 x1 = __ldg((const float4*)(g_T + soffs[w][2 * (i + 1) + half]) + q);
        float4 x2 = __ldg((const float4*)(g_T + soffs[w][2 * (i + 2) + half]) + q);
        float4 x3 = __ldg((const float4*)(g_T + soffs[w][2 * (i + 3) + half]) + q);
        a0 = mul4(a0, x0);
        a1 = mul4(a1, x1);
        a2 = mul4(a2, x2);
        a3 = mul4(a3, x3);
    }
    float4 p = mul4(mul4(a0, a1), mul4(a2, a3));

    float4 o;
    o.x = __shfl_xor_sync(0xffffffffu, p.x, 16);
    o.y = __shfl_xor_sync(0xffffffffu, p.y, 16);
    o.z = __shfl_xor_sync(0xffffffffu, p.z, 16);
    o.w = __shfl_xor_sync(0xffffffffu, p.w, 16);
    p = mul4(p, o);

    float s = (p.x + p.y) + (p.z + p.w);
    #pragma unroll
    for (int off = 8; off; off >>= 1) s += __shfl_xor_sync(0xffffffffu, s, off);
    if (lane == 0) out[b] = s;
}

extern "C" void kernel_launch(void* const* d_in, const int* in_sizes, int n_in,
                              void* d_out, int out_size)
{
    const void*  idx = d_in[0];                 // indices (B,L) int32 or int64
    const float* eps = (const float*)d_in[1];   // epsilon fp32
    float* out = (float*)d_out;
    (void)in_sizes; (void)n_in; (void)out_size;

    flag_kernel<<<B_SZ / 8, 256>>>(idx);
    transposeA_kernel<<<dim3(32, 32, 4), 256>>>(eps);
    transposeB_kernel<<<dim3(32, 64), 128>>>(eps);
    seggps_kernel<<<B_SZ / 8, 256>>>(idx, out);
}

// round 12
// speedup vs baseline: 1.8296x; 1.8296x over previous
#include <cuda_runtime.h>

// SegGPS_66949950210076
// out[b] = sum_m prod_l eps[idx[b,l], m, l, nup[b,l], ndn[b,l]]
// B=8192, L=64, M=64, LOCAL_DIM=4, eps (4,64,64,65,65) fp32.
//
// R9: bounding-box demand. Per site l, the touched (nup,ndn) set is a
// Binomial(l,1/2)^2 ellipse; we capture [min,max]nup x [min,max]ndn per l
// (256 ints, atomicMin on packed complements) and transpose ONLY the box
// (~39% of cells) into T[cell][idx][m] (256B m-contiguous, L2-resident).
// No per-cell flags anywhere. Pipeline: reset -> bounds -> boxTranspose ->
// gather (warp/batch float4 lane-split, unchanged 15.5us shape).

#define B_SZ   8192
#define L_SZ   64
#define IDX_STRIDE 17305600   // M*L*65*65
#define M_STRIDE   270400     // L*65*65
#define L_STRIDE   4225       // 65*65
#define CELLS  89440          // sum_{k=1..64} k^2
#define T_ELEMS (CELLS * 256)

__device__ __align__(256) float g_T[T_ELEMS];  // 91.6 MB scratch (static)
// g_bounds[0][l]=min nup, [1][l]=64-max nup, [2][l]=min ndn, [3][l]=64-max ndn
__device__ unsigned g_bounds[4][L_SZ];

__device__ __forceinline__ int cell_off(int l) {
    return l * (l + 1) * (2 * l + 1) / 6;      // sum_{j=1..l} j^2
}
__device__ __forceinline__ float4 mul4(float4 a, float4 b) {
    return make_float4(a.x * b.x, a.y * b.y, a.z * b.z, a.w * b.w);
}

// Per-warp dtype probe. Indices are logically int64 (ref) but JAX x64-off
// emits int32. Under int64 LE every odd 32-bit word is 0 (values < 4); under
// int32 odd words are random in [0,4). Probe 64 odd words of a fixed
// 128-word window within the first 524288 words (in-bounds either way).
// P(false int64 | int32) = 0.25^64 per warp.
__device__ __forceinline__ int probe_is_int32(const unsigned* __restrict__ w,
                                              int b, int lane) {
    int base = (b & 4095) * 128;
    unsigned x = w[base + 2 * lane + 1] | w[base + 64 + 2 * lane + 1];
    return __ballot_sync(0xffffffffu, x != 0u) != 0u;
}

// Per-warp scan of one batch: two ballots cover all 64 sites.
// Lane holds site l=lane (v0,nup0,ndn0) and site l=lane+32 (v1,nup1,ndn1).
__device__ __forceinline__ void scan_batch_raw(
    const void* idx_raw, int is32, int b, int lane,
    int& v0, int& v1, int& nup0, int& ndn0, int& nup1, int& ndn1)
{
    if (is32) {
        const int* p = (const int*)idx_raw + b * L_SZ;
        v0 = p[lane];  v1 = p[lane + 32];
    } else {
        const long long* p = (const long long*)idx_raw + (size_t)b * L_SZ;
        v0 = (int)p[lane];  v1 = (int)p[lane + 32];
    }
    unsigned bu0 = __ballot_sync(0xffffffffu, v0 & 1);
    unsigned bd0 = __ballot_sync(0xffffffffu, v0 & 2);
    unsigned bu1 = __ballot_sync(0xffffffffu, v1 & 1);
    unsigned bd1 = __ballot_sync(0xffffffffu, v1 & 2);
    unsigned mlt = (1u << lane) - 1u;
    nup0 = __popc(bu0 & mlt);               ndn0 = __popc(bd0 & mlt);
    nup1 = __popc(bu0) + __popc(bu1 & mlt); ndn1 = __popc(bd0) + __popc(bd1 & mlt);
}

// ---- reset bounds to sentinels (identity for atomicMin) ----
__global__ void reset_kernel() {
    if (threadIdx.x < 256) ((unsigned*)g_bounds)[threadIdx.x] = 64u;
}

// ---- per-l bounding boxes: CTA-reduce 8 batches, 256 atomicMin total ----
__global__ __launch_bounds__(256) void bounds_kernel(const void* __restrict__ idx_raw) {
    __shared__ unsigned red[8][64];

    const int lane = threadIdx.x & 31;
    const int w    = threadIdx.x >> 5;
    const int b    = blockIdx.x * 8 + w;

    int is32 = probe_is_int32((const unsigned*)idx_raw, b, lane);
    int v0, v1, nu0, nd0, nu1, nd1;
    scan_batch_raw(idx_raw, is32, b, lane, v0, v1, nu0, nd0, nu1, nd1);
    (void)v0; (void)v1;

    // pack (nup, 64-nup, ndn, 64-ndn) as bytes; byte-wise min == field min
    red[w][lane]      = (unsigned)(nu0 | ((64 - nu0) << 8) |
                                   (nd0 << 16) | ((64 - nd0) << 24));
    red[w][lane + 32] = (unsigned)(nu1 | ((64 - nu1) << 8) |
                                   (nd1 << 16) | ((64 - nd1) << 24));
    __syncthreads();

    if (threadIdx.x < 64) {
        const int l = threadIdx.x;
        unsigned r = red[0][l];
        #pragma unroll
        for (int k = 1; k < 8; k++) r = __vminu4(r, red[k][l]);
        atomicMin(&g_bounds[0][l],  r        & 255u);   // min nup
        atomicMin(&g_bounds[1][l], (r >>  8) & 255u);   // 64 - max nup
        atomicMin(&g_bounds[2][l], (r >> 16) & 255u);   // min ndn
        atomicMin(&g_bounds[3][l],  r >> 24        );   // 64 - max ndn
    }
}

// ---- box transpose: CTA per (l, nup, idx); smem-coalesced, box-restricted --
__global__ __launch_bounds__(256) void transpose_kernel(const float* __restrict__ eps) {
    const int l = blockIdx.x, nup = blockIdx.y, idx = blockIdx.z;
    if (nup > l) return;

    const int amin =      (int)g_bounds[0][l];
    const int amax = 64 - (int)g_bounds[1][l];
    if (nup < amin || nup > amax) return;
    const int cmin = (int)g_bounds[2][l];
    int cmax = 64 - (int)g_bounds[3][l];
    if (cmax > l) cmax = l;
    const int W = cmax - cmin + 1;         // 1..65
    if (W <= 0) return;

    const int nv = l + 1;
    const int cellbase = cell_off(l) + nup * nv;

    __shared__ float sm[64][65];           // [m][ndn-cmin], stride 65: no bank conflicts

    const int tid = threadIdx.x;
    const int c64 = tid & 63;
    const int r4  = tid >> 6;

    // read: columns cmin..cmax contiguous along ndn -> coalesced
    const float* src = eps + idx * IDX_STRIDE + l * L_STRIDE + nup * 65 + cmin;
    if (c64 < W) {
        #pragma unroll
        for (int mb = 0; mb < 64; mb += 4) {
            int m = mb + r4;
            sm[m][c64] = src[m * M_STRIDE + c64];
        }
    }
    __syncthreads();

    // write: 256B m-contiguous per box cell
    float* dst = g_T + (size_t)cellbase * 256 + idx * 64;
    for (int nb = 0; nb < W; nb += 4) {
        int k = nb + r4;                    // ndn - cmin
        if (k < W)
            dst[(cmin + k) * 256 + c64] = sm[c64][k];
    }
}

// ---- gather: warp per batch; float4, lane-split (even/odd sites) ----
__global__ __launch_bounds__(256) void seggps_kernel(
    const void* __restrict__ idx_raw,
    float*      __restrict__ out)
{
    __shared__ int soffs[8][64];

    const int lane = threadIdx.x & 31;
    const int w    = threadIdx.x >> 5;
    const int b    = blockIdx.x * 8 + w;

    int is32 = probe_is_int32((const unsigned*)idx_raw, b, lane);
    int v0, v1, nu0, nd0, nu1, nd1;
    scan_batch_raw(idx_raw, is32, b, lane, v0, v1, nu0, nd0, nu1, nd1);
    int c0 = cell_off(lane)      + nu0 * (lane + 1)  + nd0;
    int c1 = cell_off(lane + 32) + nu1 * (lane + 33) + nd1;
    soffs[w][lane]      = c0 * 256 + v0 * 64;
    soffs[w][lane + 32] = c1 * 256 + v1 * 64;
    __syncwarp();

    const int half = lane >> 4;             // 0: even sites, 1: odd sites
    const int q    = lane & 15;             // m-quad (4 floats)

    float4 a0 = make_float4(1.f, 1.f, 1.f, 1.f), a1 = a0, a2 = a0, a3 = a0;
    #pragma unroll
    for (int i = 0; i < 32; i += 4) {
        float4 x0 = __ldg((const float4*)(g_T + soffs[w][2 * (i + 0) + half]) + q);
        float4 x1 = __ldg((const float4*)(g_T + soffs[w][2 * (i + 1) + half]) + q);
        float4 x2 = __ldg((const float4*)(g_T + soffs[w][2 * (i + 2) + half]) + q);
        float4 x3 = __ldg((const float4*)(g_T + soffs[w][2 * (i + 3) + half]) + q);
        a0 = mul4(a0, x0);
        a1 = mul4(a1, x1);
        a2 = mul4(a2, x2);
        a3 = mul4(a3, x3);
    }
    float4 p = mul4(mul4(a0, a1), mul4(a2, a3));

    float4 o;
    o.x = __shfl_xor_sync(0xffffffffu, p.x, 16);
    o.y = __shfl_xor_sync(0xffffffffu, p.y, 16);
    o.z = __shfl_xor_sync(0xffffffffu, p.z, 16);
    o.w = __shfl_xor_sync(0xffffffffu, p.w, 16);
    p = mul4(p, o);

    float s = (p.x + p.y) + (p.z + p.w);
    #pragma unroll
    for (int off = 8; off; off >>= 1) s += __shfl_xor_sync(0xffffffffu, s, off);
    if (lane == 0) out[b] = s;
}

extern "C" void kernel_launch(void* const* d_in, const int* in_sizes, int n_in,
                              void* d_out, int out_size)
{
    const void*  idx = d_in[0];                 // indices (B,L) int32 or int64
    const float* eps = (const float*)d_in[1];   // epsilon fp32
    float* out = (float*)d_out;
    (void)in_sizes; (void)n_in; (void)out_size;

    reset_kernel<<<1, 256>>>();
    bounds_kernel<<<B_SZ / 8, 256>>>(idx);
    transpose_kernel<<<dim3(64, 64, 4), 256>>>(eps);
    seggps_kernel<<<B_SZ / 8, 256>>>(idx, out);
}